// round 7
// baseline (speedup 1.0000x reference)
#include <cuda_runtime.h>
#include <cuda_bf16.h>

#define NPATCH 8192
#define NTILES 128
#define NTOT   8320
#define NEDGES 1024
#define INDIM  384
#define DMODEL 256
#define NHEADS 4
#define DHEAD  64
#define MAXDEG 1024

// ---------------- scratch (static device globals; no allocation) ----------------
__device__ float g_hA[NTOT * DMODEL];           // post-GEMM h (fp32)
__device__ __nv_bfloat16 g_hAb[NTOT * DMODEL];  // bf16 copy for stage1 gathers
__device__ float g_hB[NTOT * DMODEL];           // post-layer h
__device__ float g_ssrc[NTOT * NHEADS];
__device__ float g_sdst[NTOT * NHEADS];
__device__ float g_sedg[NEDGES * NHEADS];
__device__ __nv_bfloat16 g_mb[NEDGES * DMODEL]; // bf16 edge messages for stage2 gathers
__device__ int   g_edge_mem[NEDGES * MAXDEG];
__device__ int   g_edge_cnt[NEDGES];
__device__ int   g_node_edges[NTOT * MAXDEG];
__device__ int   g_node_cnt[NTOT];

// ---------------- helpers ----------------
__device__ __forceinline__ float wsum(float v) {
#pragma unroll
    for (int o = 16; o; o >>= 1) v += __shfl_xor_sync(0xffffffffu, v, o);
    return v;
}
__device__ __forceinline__ float lrelu(float x) { return x >= 0.f ? x : 0.2f * x; }

// packed dual-FMA: acc(pair) += a(pair) * unpacked(bf16x2)   [sm_103a f32x2 pipe]
__device__ __forceinline__ void ffma2_bf(unsigned long long& acc, unsigned u,
                                         unsigned long long aw) {
    unsigned lo = u << 16;
    unsigned hi = u & 0xffff0000u;
    unsigned long long v;
    asm("mov.b64 %0, {%1,%2};" : "=l"(v) : "r"(lo), "r"(hi));
    asm("fma.rn.f32x2 %0, %1, %2, %0;" : "+l"(acc) : "l"(aw), "l"(v));
}
__device__ __forceinline__ float2 unpack2(unsigned long long p) {
    unsigned lo, hi;
    asm("mov.b64 {%0,%1}, %2;" : "=r"(lo), "=r"(hi) : "l"(p));
    float2 r;
    r.x = __uint_as_float(lo);
    r.y = __uint_as_float(hi);
    return r;
}

__device__ __forceinline__ void mma_bf16(float* c, const unsigned* a, const unsigned* b) {
    asm volatile(
        "mma.sync.aligned.m16n8k16.row.col.f32.bf16.bf16.f32 "
        "{%0,%1,%2,%3}, {%4,%5,%6,%7}, {%8,%9}, {%0,%1,%2,%3};\n"
        : "+f"(c[0]), "+f"(c[1]), "+f"(c[2]), "+f"(c[3])
        : "r"(a[0]), "r"(a[1]), "r"(a[2]), "r"(a[3]), "r"(b[0]), "r"(b[1]));
}

__device__ __forceinline__ void split_bf16(float v, __nv_bfloat16& hi, __nv_bfloat16& lo) {
    __nv_bfloat16 h = __float2bfloat16_rn(v);
    hi = h;
    lo = __float2bfloat16_rn(v - __bfloat162float(h));
}

// ---------------- fused adjacency build: CSC (blocks 0..255) + CSR (rest) ----------------
__global__ void build_kernel(const float* __restrict__ H) {
    const int tid = threadIdx.x, lane = tid & 31, wid = tid >> 5;
    if (blockIdx.x < NEDGES / 4) {
        const int e0 = blockIdx.x * 4;
        __shared__ int s_base[4];
        __shared__ int s_wcnt[8][4];
        if (tid < 4) s_base[tid] = 0;
        __syncthreads();
        for (int base = 0; base < NTOT; base += 256) {
            int n = base + tid;
            float4 v = make_float4(0.f, 0.f, 0.f, 0.f);
            if (n < NTOT) v = *(const float4*)(H + (size_t)n * NEDGES + e0);
            bool p[4] = {v.x > 0.f, v.y > 0.f, v.z > 0.f, v.w > 0.f};
            unsigned b[4];
#pragma unroll
            for (int j = 0; j < 4; j++) b[j] = __ballot_sync(0xffffffffu, p[j]);
            if (lane == 0) {
#pragma unroll
                for (int j = 0; j < 4; j++) s_wcnt[wid][j] = __popc(b[j]);
            }
            __syncthreads();
#pragma unroll
            for (int j = 0; j < 4; j++) {
                if (p[j]) {
                    int woff = 0;
                    for (int w = 0; w < wid; w++) woff += s_wcnt[w][j];
                    int pos = s_base[j] + woff + __popc(b[j] & ((1u << lane) - 1u));
                    if (pos < MAXDEG) g_edge_mem[(size_t)(e0 + j) * MAXDEG + pos] = n;
                }
            }
            __syncthreads();
            if (tid < 4) {
                int tot = 0;
                for (int w = 0; w < 8; w++) tot += s_wcnt[w][tid];
                s_base[tid] += tot;
            }
            __syncthreads();
        }
        if (tid < 4) g_edge_cnt[e0 + tid] = s_base[tid] < MAXDEG ? s_base[tid] : MAXDEG;
    } else {
        const int n = blockIdx.x - NEDGES / 4;
        const float* row = H + (size_t)n * NEDGES;
        __shared__ int s_base;
        __shared__ int s_wcnt[8];
        if (tid == 0) s_base = 0;
        __syncthreads();
        for (int base = 0; base < NEDGES; base += 256) {
            int e = base + tid;
            bool p = row[e] > 0.f;
            unsigned b = __ballot_sync(0xffffffffu, p);
            if (lane == 0) s_wcnt[wid] = __popc(b);
            __syncthreads();
            int woff = 0;
            for (int w = 0; w < wid; w++) woff += s_wcnt[w];
            if (p) {
                int pos = s_base + woff + __popc(b & ((1u << lane) - 1u));
                g_node_edges[(size_t)n * MAXDEG + pos] = e;
            }
            __syncthreads();
            if (tid == 0) {
                int tot = 0;
                for (int w = 0; w < 8; w++) tot += s_wcnt[w];
                s_base += tot;
            }
            __syncthreads();
        }
        if (tid == 0) g_node_cnt[n] = s_base;
    }
}

// ---------------- tensor-core GEMM (split-bf16) + fused s_src/s_dst epilogue ----------------
// BM=64, BN=128, BK=32 -> grid (130, 2), ~2 blocks/SM. 8 warps: wm in 0..3 owns 16 rows,
// wn in 0..1 owns one head's 64 cols -> fused per-head s dots reduce within a tg-quad.
template <int KDIM, bool FIRST>
__global__ __launch_bounds__(256) void gemm_tc_kernel(
    const float* __restrict__ A, const float* __restrict__ RO,
    const float* __restrict__ W, const float* __restrict__ nemb,
    const int* __restrict__ ntype,
    const float* __restrict__ asrc, const float* __restrict__ adst) {
    constexpr int SA = 36;
    __shared__ __nv_bfloat16 sAhi[64 * SA];
    __shared__ __nv_bfloat16 sAlo[64 * SA];
    __shared__ __nv_bfloat16 sBhi[128 * SA];  // n-major: [n][k]
    __shared__ __nv_bfloat16 sBlo[128 * SA];

    const int m0 = blockIdx.x * 64, n0 = blockIdx.y * 128;
    const int tid = threadIdx.x, lane = tid & 31, warp = tid >> 5;
    const int g = lane >> 2, tg = lane & 3;
    const int wm = warp & 3, wn = warp >> 2;
    const float* Asrc = FIRST ? A : g_hB;

    float acc[8][4];
#pragma unroll
    for (int nt = 0; nt < 8; nt++)
#pragma unroll
        for (int j = 0; j < 4; j++) acc[nt][j] = 0.f;

    const int KT = KDIM / 32;
    for (int kt = 0; kt < KT; kt++) {
        const int k0 = kt * 32;
        // A tile 64x32 fp32 -> split
#pragma unroll
        for (int i = 0; i < 2; i++) {
            int idx = tid + i * 256;
            int r = idx >> 3, kc = (idx & 7) * 4;
            int grow = m0 + r;
            float4 v;
            if (FIRST && grow >= NPATCH) v = *(const float4*)(RO + k0 + kc);
            else v = *(const float4*)(Asrc + (size_t)grow * KDIM + k0 + kc);
            float vv[4] = {v.x, v.y, v.z, v.w};
#pragma unroll
            for (int j = 0; j < 4; j++) {
                __nv_bfloat16 hi, lo;
                split_bf16(vv[j], hi, lo);
                sAhi[r * SA + kc + j] = hi;
                sAlo[r * SA + kc + j] = lo;
            }
        }
        // W tile 32x128 fp32 -> split + transpose to [n][k]
#pragma unroll
        for (int i = 0; i < 4; i++) {
            int idx = tid + i * 256;
            int k = idx >> 5, nq = (idx & 31) * 4;
            float4 v = *(const float4*)(W + (size_t)(k0 + k) * DMODEL + n0 + nq);
            float vv[4] = {v.x, v.y, v.z, v.w};
#pragma unroll
            for (int j = 0; j < 4; j++) {
                __nv_bfloat16 hi, lo;
                split_bf16(vv[j], hi, lo);
                sBhi[(nq + j) * SA + k] = hi;
                sBlo[(nq + j) * SA + k] = lo;
            }
        }
        __syncthreads();

#pragma unroll
        for (int ks = 0; ks < 2; ks++) {
            const int kb = ks * 16;
            unsigned ahi[4], alo[4];
            int r0 = wm * 16 + g;
            ahi[0] = *(const unsigned*)&sAhi[r0 * SA + kb + 2 * tg];
            ahi[1] = *(const unsigned*)&sAhi[(r0 + 8) * SA + kb + 2 * tg];
            ahi[2] = *(const unsigned*)&sAhi[r0 * SA + kb + 2 * tg + 8];
            ahi[3] = *(const unsigned*)&sAhi[(r0 + 8) * SA + kb + 2 * tg + 8];
            alo[0] = *(const unsigned*)&sAlo[r0 * SA + kb + 2 * tg];
            alo[1] = *(const unsigned*)&sAlo[(r0 + 8) * SA + kb + 2 * tg];
            alo[2] = *(const unsigned*)&sAlo[r0 * SA + kb + 2 * tg + 8];
            alo[3] = *(const unsigned*)&sAlo[(r0 + 8) * SA + kb + 2 * tg + 8];
#pragma unroll
            for (int nt = 0; nt < 8; nt++) {
                int n = wn * 64 + nt * 8 + g;
                unsigned bhi[2], blo[2];
                bhi[0] = *(const unsigned*)&sBhi[n * SA + kb + 2 * tg];
                bhi[1] = *(const unsigned*)&sBhi[n * SA + kb + 2 * tg + 8];
                blo[0] = *(const unsigned*)&sBlo[n * SA + kb + 2 * tg];
                blo[1] = *(const unsigned*)&sBlo[n * SA + kb + 2 * tg + 8];
                mma_bf16(acc[nt], alo, bhi);
                mma_bf16(acc[nt], ahi, blo);
                mma_bf16(acc[nt], ahi, bhi);
            }
        }
        __syncthreads();
    }

    // epilogue: + node_emb[type], fp32 + bf16 writes; fused per-head s_src/s_dst dots
    const int h = 2 * blockIdx.y + wn;
    {
        int r_a = m0 + wm * 16 + g;
        int r_b = r_a + 8;
        int ta = ntype[r_a], tb = ntype[r_b];
        float ssa = 0.f, ssb = 0.f, sda = 0.f, sdb = 0.f;
#pragma unroll
        for (int nt = 0; nt < 8; nt++) {
            int c = n0 + wn * 64 + nt * 8 + 2 * tg;
            int d = nt * 8 + 2 * tg;
            float v0 = acc[nt][0] + nemb[ta * DMODEL + c];
            float v1 = acc[nt][1] + nemb[ta * DMODEL + c + 1];
            float v2 = acc[nt][2] + nemb[tb * DMODEL + c];
            float v3 = acc[nt][3] + nemb[tb * DMODEL + c + 1];
            *(float2*)&g_hA[(size_t)r_a * DMODEL + c] = make_float2(v0, v1);
            *(float2*)&g_hA[(size_t)r_b * DMODEL + c] = make_float2(v2, v3);
            __nv_bfloat162 ba, bb;
            ba.x = __float2bfloat16_rn(v0); ba.y = __float2bfloat16_rn(v1);
            bb.x = __float2bfloat16_rn(v2); bb.y = __float2bfloat16_rn(v3);
            *(__nv_bfloat162*)&g_hAb[(size_t)r_a * DMODEL + c] = ba;
            *(__nv_bfloat162*)&g_hAb[(size_t)r_b * DMODEL + c] = bb;
            float as0 = asrc[h * DHEAD + d], as1 = asrc[h * DHEAD + d + 1];
            float ad0 = adst[h * DHEAD + d], ad1 = adst[h * DHEAD + d + 1];
            ssa += v0 * as0 + v1 * as1;
            ssb += v2 * as0 + v3 * as1;
            sda += v0 * ad0 + v1 * ad1;
            sdb += v2 * ad0 + v3 * ad1;
        }
#pragma unroll
        for (int o = 1; o <= 2; o <<= 1) {
            ssa += __shfl_xor_sync(0xffffffffu, ssa, o);
            ssb += __shfl_xor_sync(0xffffffffu, ssb, o);
            sda += __shfl_xor_sync(0xffffffffu, sda, o);
            sdb += __shfl_xor_sync(0xffffffffu, sdb, o);
        }
        if (tg == 0) {
            g_ssrc[r_a * NHEADS + h] = ssa;
            g_ssrc[r_b * NHEADS + h] = ssb;
            g_sdst[r_a * NHEADS + h] = sda;
            g_sdst[r_b * NHEADS + h] = sdb;
        }
    }
}

// ---------------- stage 1: node -> edge, single-pass, 8 cols/thread, f32x2 FMA ----------------
__global__ void stage1_kernel(const float* __restrict__ ebias, const int* __restrict__ etype,
                              const float* __restrict__ aedg) {
    const int e = blockIdx.x;
    const int tid = threadIdx.x, lane = tid & 31, wid = tid >> 5;
    const int cnt = g_edge_cnt[e];
    __shared__ float s_eb[4], s_inv[4];
    __shared__ float s_red[8][4];
    __shared__ uint2 s_pairs[4 * 256];   // per head: (row offset in uint4 units, weight bits)
    __shared__ float s_part[8 * 256];
    if (tid < 4) s_eb[tid] = ebias[etype[e] * 4 + tid];
    __syncthreads();
    const int* mem = g_edge_mem + (size_t)e * MAXDEG;

    const int o = tid & 31;        // column oct: cols 8o..8o+7
    const int slice = tid >> 5;    // member slice 0..7
    const int hq = o >> 3;         // head of this oct
    const uint4* basep = (const uint4*)g_hAb + o;
    unsigned long long A01 = 0ull, A23 = 0ull, A45 = 0ull, A67 = 0ull;
    float w0 = 0.f, w1 = 0.f, w2 = 0.f, w3 = 0.f;

    for (int base = 0; base < cnt; base += 256) {
        int i = base + tid;
        if (i < cnt) {
            int n = mem[i];
            unsigned off = (unsigned)n * (DMODEL / 8);
            float4 ss = *(const float4*)(g_ssrc + n * 4);
            float e0 = __expf(lrelu(ss.x + s_eb[0]));
            float e1 = __expf(lrelu(ss.y + s_eb[1]));
            float e2 = __expf(lrelu(ss.z + s_eb[2]));
            float e3 = __expf(lrelu(ss.w + s_eb[3]));
            s_pairs[0 * 256 + tid] = make_uint2(off, __float_as_uint(e0));
            s_pairs[1 * 256 + tid] = make_uint2(off, __float_as_uint(e1));
            s_pairs[2 * 256 + tid] = make_uint2(off, __float_as_uint(e2));
            s_pairs[3 * 256 + tid] = make_uint2(off, __float_as_uint(e3));
            w0 += e0; w1 += e1; w2 += e2; w3 += e3;
        }
        __syncthreads();
        int lim = min(256, cnt - base);
#pragma unroll 4
        for (int j = slice; j < lim; j += 8) {
            uint2 pw = s_pairs[hq * 256 + j];
            unsigned long long aw;
            asm("mov.b64 %0, {%1,%1};" : "=l"(aw) : "r"(pw.y));
            uint4 u = basep[pw.x];
            ffma2_bf(A01, u.x, aw);
            ffma2_bf(A23, u.y, aw);
            ffma2_bf(A45, u.z, aw);
            ffma2_bf(A67, u.w, aw);
        }
        __syncthreads();
    }

    w0 = wsum(w0); w1 = wsum(w1); w2 = wsum(w2); w3 = wsum(w3);
    if (lane == 0) { s_red[wid][0] = w0; s_red[wid][1] = w1; s_red[wid][2] = w2; s_red[wid][3] = w3; }
    float* pp = s_part + slice * 256 + o * 8;
    float2 p01 = unpack2(A01), p23 = unpack2(A23), p45 = unpack2(A45), p67 = unpack2(A67);
    pp[0] = p01.x; pp[1] = p01.y; pp[2] = p23.x; pp[3] = p23.y;
    pp[4] = p45.x; pp[5] = p45.y; pp[6] = p67.x; pp[7] = p67.y;
    __syncthreads();
    if (tid < 4) {
        float t = 0.f;
        for (int w = 0; w < 8; w++) t += s_red[w][tid];
        s_inv[tid] = 1.f / t;
    }
    __syncthreads();
    const int c = tid;
    float m_c = 0.f;
#pragma unroll
    for (int s = 0; s < 8; s++) m_c += s_part[s * 256 + c];
    m_c *= s_inv[c >> 6];
    g_mb[(size_t)e * DMODEL + c] = __float2bfloat16_rn(m_c);

    float se = m_c * aedg[c];
    se = wsum(se);
    if (lane == 0) s_red[wid][0] = se;
    __syncthreads();
    if (tid < 4) g_sedg[e * 4 + tid] = s_red[2 * tid][0] + s_red[2 * tid + 1][0];
}

// ---------------- stage 2: edge -> node, single-pass, f32x2 FMA + ELU + residual ----------------
__global__ void stage2_kernel() {
    const int n = blockIdx.x;
    const int tid = threadIdx.x, lane = tid & 31, wid = tid >> 5;
    const int cnt = g_node_cnt[n];
    __shared__ float s_sd[4], s_inv[4];
    __shared__ float s_red[8][4];
    __shared__ uint2 s_pairs[4 * 256];
    __shared__ float s_part[8 * 256];
    if (tid < 4) s_sd[tid] = g_sdst[n * 4 + tid];
    __syncthreads();
    const int* el = g_node_edges + (size_t)n * MAXDEG;

    const int o = tid & 31;
    const int slice = tid >> 5;
    const int hq = o >> 3;
    const uint4* basep = (const uint4*)g_mb + o;
    unsigned long long A01 = 0ull, A23 = 0ull, A45 = 0ull, A67 = 0ull;
    float w0 = 0.f, w1 = 0.f, w2 = 0.f, w3 = 0.f;

    for (int base = 0; base < cnt; base += 256) {
        int i = base + tid;
        if (i < cnt) {
            int e = el[i];
            unsigned off = (unsigned)e * (DMODEL / 8);
            float4 sg = *(const float4*)(g_sedg + e * 4);
            float e0 = __expf(lrelu(s_sd[0] + sg.x));
            float e1 = __expf(lrelu(s_sd[1] + sg.y));
            float e2 = __expf(lrelu(s_sd[2] + sg.z));
            float e3 = __expf(lrelu(s_sd[3] + sg.w));
            s_pairs[0 * 256 + tid] = make_uint2(off, __float_as_uint(e0));
            s_pairs[1 * 256 + tid] = make_uint2(off, __float_as_uint(e1));
            s_pairs[2 * 256 + tid] = make_uint2(off, __float_as_uint(e2));
            s_pairs[3 * 256 + tid] = make_uint2(off, __float_as_uint(e3));
            w0 += e0; w1 += e1; w2 += e2; w3 += e3;
        }
        __syncthreads();
        int lim = min(256, cnt - base);
#pragma unroll 4
        for (int j = slice; j < lim; j += 8) {
            uint2 pw = s_pairs[hq * 256 + j];
            unsigned long long aw;
            asm("mov.b64 %0, {%1,%1};" : "=l"(aw) : "r"(pw.y));
            uint4 u = basep[pw.x];
            ffma2_bf(A01, u.x, aw);
            ffma2_bf(A23, u.y, aw);
            ffma2_bf(A45, u.z, aw);
            ffma2_bf(A67, u.w, aw);
        }
        __syncthreads();
    }

    w0 = wsum(w0); w1 = wsum(w1); w2 = wsum(w2); w3 = wsum(w3);
    if (lane == 0) { s_red[wid][0] = w0; s_red[wid][1] = w1; s_red[wid][2] = w2; s_red[wid][3] = w3; }
    float* pp = s_part + slice * 256 + o * 8;
    float2 p01 = unpack2(A01), p23 = unpack2(A23), p45 = unpack2(A45), p67 = unpack2(A67);
    pp[0] = p01.x; pp[1] = p01.y; pp[2] = p23.x; pp[3] = p23.y;
    pp[4] = p45.x; pp[5] = p45.y; pp[6] = p67.x; pp[7] = p67.y;
    __syncthreads();
    if (tid < 4) {
        float t = 0.f;
        for (int w = 0; w < 8; w++) t += s_red[w][tid];
        s_inv[tid] = 1.f / t;
    }
    __syncthreads();
    const int c = tid;
    float acc = 0.f;
#pragma unroll
    for (int s = 0; s < 8; s++) acc += s_part[s * 256 + c];
    acc *= s_inv[c >> 6];
    float o2 = acc > 0.f ? acc : (__expf(acc) - 1.f);       // ELU(alpha=1)
    g_hB[(size_t)n * DMODEL + c] = o2 + g_hA[(size_t)n * DMODEL + c];
}

// ---------------- final layer norm ----------------
__global__ void ln_kernel(const float* __restrict__ ng, const float* __restrict__ nb,
                          const float* __restrict__ bg, const float* __restrict__ bb,
                          float* __restrict__ out) {
    const int n = blockIdx.x;
    const int tid = threadIdx.x, lane = tid & 31, wid = tid >> 5;
    __shared__ float sred[8];
    __shared__ float s_mean, s_rstd;
    float x = g_hB[(size_t)n * DMODEL + tid];
    float s = wsum(x);
    if (lane == 0) sred[wid] = s;
    __syncthreads();
    if (tid == 0) {
        float t = 0.f;
        for (int w = 0; w < 8; w++) t += sred[w];
        s_mean = t * (1.f / DMODEL);
    }
    __syncthreads();
    float c = x - s_mean;
    float v = wsum(c * c);
    if (lane == 0) sred[wid] = v;
    __syncthreads();
    if (tid == 0) {
        float t = 0.f;
        for (int w = 0; w < 8; w++) t += sred[w];
        s_rstd = rsqrtf(t * (1.f / DMODEL) + 1e-5f);
    }
    __syncthreads();
    const float* g = (n < NPATCH) ? ng : bg;
    const float* b = (n < NPATCH) ? nb : bb;
    out[(size_t)n * DMODEL + tid] = c * s_rstd * g[tid] + b[tid];
}

// ---------------- launcher ----------------
extern "C" void kernel_launch(void* const* d_in, const int* in_sizes, int n_in,
                              void* d_out, int out_size) {
    const float* x_nodes = (const float*)d_in[0];
    const float* ro      = (const float*)d_in[1];
    const int*   ntype   = (const int*)d_in[2];
    const int*   etype   = (const int*)d_in[3];
    const float* H       = (const float*)d_in[4];
    // d_in[5] readout_node_ids == arange(8192, 8320)
    const float* W0      = (const float*)d_in[6];
    const float* W1      = (const float*)d_in[7];
    const float* nemb    = (const float*)d_in[8];
    const float* asrc    = (const float*)d_in[9];
    const float* adst    = (const float*)d_in[10];
    const float* aedg    = (const float*)d_in[11];
    const float* ebias   = (const float*)d_in[12];
    const float* ngam    = (const float*)d_in[13];
    const float* nbet    = (const float*)d_in[14];
    const float* bgam    = (const float*)d_in[15];
    const float* bbet    = (const float*)d_in[16];
    float* out = (float*)d_out;

    // stage2 (layer 0) stays at our #3 = profiled slot for direct f32x2 verification
    build_kernel<<<NEDGES / 4 + NTOT, 256>>>(H);                                // #0
    gemm_tc_kernel<INDIM, true><<<dim3(NTOT / 64, DMODEL / 128), 256>>>(
        x_nodes, ro, W0, nemb + 0 * 4 * DMODEL, ntype, asrc, adst);             // #1
    stage1_kernel<<<NEDGES, 256>>>(ebias, etype, aedg);                         // #2
    stage2_kernel<<<NTOT, 256>>>();                                             // #3 (profiled)

    gemm_tc_kernel<DMODEL, false><<<dim3(NTOT / 64, DMODEL / 128), 256>>>(
        nullptr, nullptr, W1, nemb + 1 * 4 * DMODEL, ntype,
        asrc + NHEADS * DHEAD, adst + NHEADS * DHEAD);                          // #4
    stage1_kernel<<<NEDGES, 256>>>(ebias + 3 * NHEADS, etype, aedg + NHEADS * DHEAD);
    stage2_kernel<<<NTOT, 256>>>();

    ln_kernel<<<NTOT, 256>>>(ngam, nbet, bgam, bbet, out);
}